// round 3
// baseline (speedup 1.0000x reference)
#include <cuda_runtime.h>
#include <cstdint>

// Problem constants
#define NVEH 16384
#define NT   256
#define HDIM 20

// 1 thread = 1 vehicle. 32 threads/block -> 512 blocks spread over 148 SMs.
#define TPB  32
#define NBLK (NVEH / TPB)   // 512

// ---------- packed f32x2 helpers (sm_103a) ----------
__device__ __forceinline__ void ffma2(unsigned long long& d,
                                      unsigned long long a,
                                      unsigned long long b) {
    asm("fma.rn.f32x2 %0, %1, %2, %0;" : "+l"(d) : "l"(a), "l"(b));
}
__device__ __forceinline__ unsigned long long dup2(float x) {
    unsigned long long r;
    asm("mov.b64 %0, {%1, %1};" : "=l"(r) : "f"(x));
    return r;
}
__device__ __forceinline__ float lo32(unsigned long long v) {
    float f;
    asm("{ .reg .b32 hi; mov.b64 {%0, hi}, %1; }" : "=f"(f) : "l"(v));
    return f;
}
__device__ __forceinline__ float hi32(unsigned long long v) {
    float f;
    asm("{ .reg .b32 lo; mov.b64 {lo, %0}, %1; }" : "=f"(f) : "l"(v));
    return f;
}

// ---------- HW tanh (MUFU.TANH) activations ----------
__device__ __forceinline__ float fast_tanh(float x) {
    float y;
    asm("tanh.approx.f32 %0, %1;" : "=f"(y) : "f"(x));
    return y;
}
// sigmoid(x) = 0.5 * tanh(x/2) + 0.5
__device__ __forceinline__ float fast_sig(float x) {
    return fmaf(0.5f, fast_tanh(0.5f * x), 0.5f);
}

__global__ __launch_bounds__(TPB)
void rnncf_kernel(const float* __restrict__ lead_inputs,  // (NVEH, NT, 2)
                  const float* __restrict__ init_state,   // (NVEH, 2)
                  const float* __restrict__ h0,           // (NVEH, H)
                  const float* __restrict__ c0,           // (NVEH, H)
                  const float* __restrict__ W,            // (3, 80)
                  const float* __restrict__ U,            // (20, 80)
                  const float* __restrict__ b,            // (80,)
                  const float* __restrict__ Wd,           // (20, 1)
                  const float* __restrict__ bd,           // (1,)
                  float* __restrict__ out,
                  int out_size)
{
    // Two packed weight tables, warp-uniform access.
    // Row k (0..23): 0..2 = W rows, 3..22 = U rows, 23 = bias.
    // tif[k][up] = ulonglong2 { pair(Wi[k,2up],Wf[k,2up]), pair(Wi[k,2up+1],Wf[k,2up+1]) }
    // tgo analogous for gates (g,o).
    __shared__ ulonglong2 tif[24 * 10];   // 3840 B
    __shared__ ulonglong2 tgo[24 * 10];   // 3840 B
    __shared__ float      wds[HDIM];

    {
        float* fif = reinterpret_cast<float*>(tif);
        float* fgo = reinterpret_cast<float*>(tgo);
        for (int idx = threadIdx.x; idx < 24 * 40; idx += TPB) {
            int k = idx / 40, r = idx % 40;
            int u = r >> 1, s = r & 1;           // s=0 -> first gate, s=1 -> second
            const float* row = (k < 3) ? (W + k * 80)
                             : (k < 23) ? (U + (k - 3) * 80)
                             : b;
            fif[idx] = row[(s ? 20 : 0) + u];    // i / f
            fgo[idx] = row[(s ? 60 : 40) + u];   // g / o
        }
        if (threadIdx.x < HDIM) wds[threadIdx.x] = Wd[threadIdx.x];
    }
    __syncthreads();

    const int v = blockIdx.x * TPB + threadIdx.x;

    float hh[HDIM], cc[HDIM];
#pragma unroll
    for (int u = 0; u < HDIM; ++u) {
        hh[u] = h0[v * HDIM + u];
        cc[u] = c0[v * HDIM + u];
    }
    const float bdv = bd[0];
    float pos = init_state[2 * v];
    float spd = init_state[2 * v + 1];

    const float2* lead2 = reinterpret_cast<const float2*>(lead_inputs) + (size_t)v * NT;
    float2 cur = lead2[0];

    const bool write_extras = (out_size >= NT * NVEH + NVEH + 2 * NVEH * HDIM);

#pragma unroll 1
    for (int t = 0; t < NT; ++t) {
        const int tn = (t + 1 < NT) ? (t + 1) : (NT - 1);
        float2 nxt = lead2[tn];   // prefetch

        const float x0 = (cur.x - pos) * (1.0f / 100.0f);
        const float x1 = spd * (1.0f / 40.0f);
        const float x2 = cur.y * (1.0f / 40.0f);

        // One input row of one table: 10 uniform LDS.128 + 20 FFMA2
#define ROWP(tab, r, mv)                                       \
        {                                                      \
            unsigned long long md = dup2(mv);                  \
            _Pragma("unroll")                                  \
            for (int up = 0; up < 10; ++up) {                  \
                ulonglong2 w = tab[(r) * 10 + up];             \
                ffma2(acc[2 * up],     w.x, md);               \
                ffma2(acc[2 * up + 1], w.y, md);               \
            }                                                  \
        }

        float si[HDIM];
        {   // ---- Pass A: gates (i, f) ----
            unsigned long long acc[HDIM];
#pragma unroll
            for (int up = 0; up < 10; ++up) {
                ulonglong2 bb = tif[23 * 10 + up];
                acc[2 * up] = bb.x; acc[2 * up + 1] = bb.y;
            }
            ROWP(tif, 0, x0) ROWP(tif, 1, x1) ROWP(tif, 2, x2)
#pragma unroll
            for (int k = 0; k < HDIM; ++k) { ROWP(tif, 3 + k, hh[k]) }
#pragma unroll
            for (int u = 0; u < HDIM; ++u) {
                si[u]  = fast_sig(lo32(acc[u]));        // sig(i)
                cc[u] *= fast_sig(hi32(acc[u]));        // sig(f) * c
            }
        }

        float p = 0.0f;
        {   // ---- Pass B: gates (g, o) ----
            unsigned long long acc[HDIM];
#pragma unroll
            for (int up = 0; up < 10; ++up) {
                ulonglong2 bb = tgo[23 * 10 + up];
                acc[2 * up] = bb.x; acc[2 * up + 1] = bb.y;
            }
            ROWP(tgo, 0, x0) ROWP(tgo, 1, x1) ROWP(tgo, 2, x2)
#pragma unroll
            for (int k = 0; k < HDIM; ++k) { ROWP(tgo, 3 + k, hh[k]) }
#pragma unroll
            for (int u = 0; u < HDIM; ++u) {
                float tg = fast_tanh(lo32(acc[u]));     // tanh(g)
                float so = fast_sig(hi32(acc[u]));      // sig(o)
                float cn = fmaf(si[u], tg, cc[u]);
                cc[u] = cn;
                float hn = so * fast_tanh(cn);
                hh[u] = hn;
                p = fmaf(hn, wds[u], p);
            }
        }
#undef ROWP

        const float o_scalar = p + bdv;
        const float a = fmaf(7.0f, o_scalar, -4.0f);   // (MAXA-MINA)*out + MINA
        spd = fmaf(0.1f, a, spd);
        pos = fmaf(0.1f, a, pos);

        out[(size_t)t * NVEH + v] = pos;   // coalesced across the warp

        cur = nxt;
    }

    if (write_extras) {
        out[(size_t)NT * NVEH + v] = spd;
        float* hout = out + (size_t)NT * NVEH + NVEH;
        float* cout = hout + (size_t)NVEH * HDIM;
#pragma unroll
        for (int u = 0; u < HDIM; ++u) {
            hout[v * HDIM + u] = hh[u];
            cout[v * HDIM + u] = cc[u];
        }
    }
}

extern "C" void kernel_launch(void* const* d_in, const int* in_sizes, int n_in,
                              void* d_out, int out_size) {
    const float* lead_inputs = (const float*)d_in[0];
    const float* init_state  = (const float*)d_in[1];
    const float* h0          = (const float*)d_in[2];
    const float* c0          = (const float*)d_in[3];
    const float* W           = (const float*)d_in[4];
    const float* U           = (const float*)d_in[5];
    const float* b           = (const float*)d_in[6];
    const float* Wd          = (const float*)d_in[7];
    const float* bd          = (const float*)d_in[8];

    rnncf_kernel<<<NBLK, TPB>>>(lead_inputs, init_state, h0, c0,
                                W, U, b, Wd, bd,
                                (float*)d_out, out_size);
}

// round 4
// speedup vs baseline: 5.6402x; 5.6402x over previous
#include <cuda_runtime.h>
#include <cstdint>

// Problem constants
#define NVEH 16384
#define NT   256
#define HDIM 20

// 1 thread = 1 vehicle, 1 warp per block.
#define TPB  32
#define NBLK (NVEH / TPB)   // 512

// Packed constant tables: row k (0..23): 0..2 = W rows, 3..22 = U rows, 23 = bias.
// IF[k*40 + 2u+s] = gate(i if s==0 else f) weight for unit u.
// GO analogous for (g,o).
struct alignas(16) CParams {
    float IF[24 * 40];
    float GO[24 * 40];
    float WdBd[24];        // [0..19] = Wd, [20] = bd
};
__constant__ CParams cP;
__device__ float gStage[24 * 40 * 2 + 24];

// ---------- packed f32x2 helpers (sm_103a) ----------
__device__ __forceinline__ void ffma2(unsigned long long& d,
                                      unsigned long long a,
                                      unsigned long long b) {
    asm("fma.rn.f32x2 %0, %1, %2, %0;" : "+l"(d) : "l"(a), "l"(b));
}
__device__ __forceinline__ unsigned long long dup2(float x) {
    unsigned long long r;
    asm("mov.b64 %0, {%1, %1};" : "=l"(r) : "f"(x));
    return r;
}
__device__ __forceinline__ float lo32(unsigned long long v) {
    float f;
    asm("{ .reg .b32 hi; mov.b64 {%0, hi}, %1; }" : "=f"(f) : "l"(v));
    return f;
}
__device__ __forceinline__ float hi32(unsigned long long v) {
    float f;
    asm("{ .reg .b32 lo; mov.b64 {lo, %0}, %1; }" : "=f"(f) : "l"(v));
    return f;
}

// ---------- HW tanh (MUFU.TANH) activations ----------
__device__ __forceinline__ float fast_tanh(float x) {
    float y;
    asm("tanh.approx.f32 %0, %1;" : "=f"(y) : "f"(x));
    return y;
}
__device__ __forceinline__ float fast_sig(float x) {
    return fmaf(0.5f, fast_tanh(0.5f * x), 0.5f);
}

// ---------- repack kernel: interleave gates into staging ----------
__global__ void repack_kernel(const float* __restrict__ W,
                              const float* __restrict__ U,
                              const float* __restrict__ b,
                              const float* __restrict__ Wd,
                              const float* __restrict__ bd)
{
    for (int idx = threadIdx.x; idx < 24 * 40; idx += blockDim.x) {
        int k = idx / 40, r = idx % 40;
        int u = r >> 1, s = r & 1;
        const float* row = (k < 3) ? (W + k * 80)
                         : (k < 23) ? (U + (k - 3) * 80)
                         : b;
        gStage[idx]            = row[(s ? 20 : 0) + u];   // i / f
        gStage[24 * 40 + idx]  = row[(s ? 60 : 40) + u];  // g / o
    }
    if (threadIdx.x < HDIM) gStage[2 * 24 * 40 + threadIdx.x] = Wd[threadIdx.x];
    if (threadIdx.x == HDIM) gStage[2 * 24 * 40 + HDIM] = bd[0];
}

__global__ __launch_bounds__(TPB, 12)
void rnncf_kernel(const float* __restrict__ lead_inputs,  // (NVEH, NT, 2)
                  const float* __restrict__ init_state,   // (NVEH, 2)
                  const float* __restrict__ h0,           // (NVEH, H)
                  const float* __restrict__ c0,           // (NVEH, H)
                  float* __restrict__ out,
                  int out_size)
{
    // Per-lane hidden state column in smem: hsm[k*32 + lane].
    // Each lane only touches its own column -> 1 wavefront per row read,
    // no cross-thread sharing, no syncs.
    __shared__ float hsm[HDIM * TPB];   // 2560 B

    const int lane = threadIdx.x;
    const int v    = blockIdx.x * TPB + lane;

    const ulonglong2* __restrict__ Tif = reinterpret_cast<const ulonglong2*>(cP.IF);
    const ulonglong2* __restrict__ Tgo = reinterpret_cast<const ulonglong2*>(cP.GO);

    float cc[HDIM];
#pragma unroll
    for (int u = 0; u < HDIM; ++u) {
        hsm[u * TPB + lane] = h0[v * HDIM + u];
        cc[u] = c0[v * HDIM + u];
    }
    const float bdv = cP.WdBd[HDIM];
    float pos = init_state[2 * v];
    float spd = init_state[2 * v + 1];

    const float2* lead2 = reinterpret_cast<const float2*>(lead_inputs) + (size_t)v * NT;
    float2 cur = lead2[0];

    const bool write_extras = (out_size >= NT * NVEH + NVEH + 2 * NVEH * HDIM);

#pragma unroll 1
    for (int t = 0; t < NT; ++t) {
        const int tn = (t + 1 < NT) ? (t + 1) : (NT - 1);
        float2 nxt = lead2[tn];   // prefetch

        const float x0 = (cur.x - pos) * (1.0f / 100.0f);
        const float x1 = spd * (1.0f / 40.0f);
        const float x2 = cur.y * (1.0f / 40.0f);

        // One row: 10 uniform const loads (16B) + 20 FFMA2
#define ROWP(tab, r, mv)                                       \
        {                                                      \
            unsigned long long md = dup2(mv);                  \
            _Pragma("unroll")                                  \
            for (int up = 0; up < 10; ++up) {                  \
                ulonglong2 w = (tab)[(r) * 10 + up];           \
                ffma2(acc[2 * up],     w.x, md);               \
                ffma2(acc[2 * up + 1], w.y, md);               \
            }                                                  \
        }

        float si[HDIM];
        {   // ---- Pass A: gates (i, f) ----
            unsigned long long acc[HDIM];
#pragma unroll
            for (int up = 0; up < 10; ++up) {
                ulonglong2 bb = Tif[23 * 10 + up];
                acc[2 * up] = bb.x; acc[2 * up + 1] = bb.y;
            }
            ROWP(Tif, 0, x0) ROWP(Tif, 1, x1) ROWP(Tif, 2, x2)
#pragma unroll 2
            for (int k = 0; k < HDIM; ++k) {
                float hk = hsm[k * TPB + lane];
                ROWP(Tif, 3 + k, hk)
            }
#pragma unroll
            for (int u = 0; u < HDIM; ++u) {
                si[u]  = fast_sig(lo32(acc[u]));        // sig(i)
                cc[u] *= fast_sig(hi32(acc[u]));        // sig(f) * c
            }
        }

        float p = 0.0f;
        {   // ---- Pass B: gates (g, o) ----
            unsigned long long acc[HDIM];
#pragma unroll
            for (int up = 0; up < 10; ++up) {
                ulonglong2 bb = Tgo[23 * 10 + up];
                acc[2 * up] = bb.x; acc[2 * up + 1] = bb.y;
            }
            ROWP(Tgo, 0, x0) ROWP(Tgo, 1, x1) ROWP(Tgo, 2, x2)
#pragma unroll 2
            for (int k = 0; k < HDIM; ++k) {
                float hk = hsm[k * TPB + lane];
                ROWP(Tgo, 3 + k, hk)
            }
#pragma unroll
            for (int u = 0; u < HDIM; ++u) {
                float tg = fast_tanh(lo32(acc[u]));     // tanh(g)
                float so = fast_sig(hi32(acc[u]));      // sig(o)
                float cn = fmaf(si[u], tg, cc[u]);
                cc[u] = cn;
                float hn = so * fast_tanh(cn);
                hsm[u * TPB + lane] = hn;
                p = fmaf(hn, cP.WdBd[u], p);
            }
        }
#undef ROWP

        const float o_scalar = p + bdv;
        const float a = fmaf(7.0f, o_scalar, -4.0f);   // (MAXA-MINA)*out + MINA
        spd = fmaf(0.1f, a, spd);
        pos = fmaf(0.1f, a, pos);

        out[(size_t)t * NVEH + v] = pos;   // coalesced across the warp

        cur = nxt;
    }

    if (write_extras) {
        out[(size_t)NT * NVEH + v] = spd;
        float* hout = out + (size_t)NT * NVEH + NVEH;
        float* cout = hout + (size_t)NVEH * HDIM;
#pragma unroll
        for (int u = 0; u < HDIM; ++u) {
            hout[v * HDIM + u] = hsm[u * TPB + lane];
            cout[v * HDIM + u] = cc[u];
        }
    }
}

extern "C" void kernel_launch(void* const* d_in, const int* in_sizes, int n_in,
                              void* d_out, int out_size) {
    const float* lead_inputs = (const float*)d_in[0];
    const float* init_state  = (const float*)d_in[1];
    const float* h0          = (const float*)d_in[2];
    const float* c0          = (const float*)d_in[3];
    const float* W           = (const float*)d_in[4];
    const float* U           = (const float*)d_in[5];
    const float* b           = (const float*)d_in[6];
    const float* Wd          = (const float*)d_in[7];
    const float* bd          = (const float*)d_in[8];

    // 1) repack weights into staging (device global)
    repack_kernel<<<1, 128>>>(W, U, b, Wd, bd);

    // 2) staging -> __constant__ (graph-capturable async D2D memcpy)
    void* stage_addr = nullptr;
    cudaGetSymbolAddress(&stage_addr, gStage);
    cudaMemcpyToSymbolAsync(cP, stage_addr, sizeof(CParams), 0,
                            cudaMemcpyDeviceToDevice, 0);

    // 3) main recurrent kernel
    rnncf_kernel<<<NBLK, TPB>>>(lead_inputs, init_state, h0, c0,
                                (float*)d_out, out_size);
}

// round 5
// speedup vs baseline: 15.5357x; 2.7545x over previous
#include <cuda_runtime.h>
#include <cstdint>

// Problem constants
#define NVEH 16384
#define NT   256
#define H    20

#define VPC  64                 // vehicles per CTA
#define TPC  160                // threads per CTA = 8 groups x 20 units
#define NCTA (NVEH / VPC)       // 256
#define VPT  8                  // vehicles per thread

typedef unsigned long long ull;

// Packed weight tables (built once per launch by repack kernel):
// per unit u (0..19): 24 IF pairs (slot3 = 0), 24 GO pairs, biasIF, biasGO.
__device__ float2 gWt[20 * 50];
__device__ float  gWd[24];      // Wd[0..19], bd at [20]

// ---------- packed f32x2 helpers (sm_103a) ----------
__device__ __forceinline__ void ffma2(ull& d, ull a, ull b) {
    asm("fma.rn.f32x2 %0, %1, %2, %0;" : "+l"(d) : "l"(a), "l"(b));
}
__device__ __forceinline__ ull dup2(float x) {
    ull r; asm("mov.b64 %0, {%1, %1};" : "=l"(r) : "f"(x)); return r;
}
__device__ __forceinline__ float lo32(ull v) {
    float f; asm("{ .reg .b32 hi; mov.b64 {%0, hi}, %1; }" : "=f"(f) : "l"(v)); return f;
}
__device__ __forceinline__ float hi32(ull v) {
    float f; asm("{ .reg .b32 lo; mov.b64 {lo, %0}, %1; }" : "=f"(f) : "l"(v)); return f;
}

// ---------- HW tanh (MUFU.TANH) activations ----------
__device__ __forceinline__ float fast_tanh(float x) {
    float y; asm("tanh.approx.f32 %0, %1;" : "=f"(y) : "f"(x)); return y;
}
__device__ __forceinline__ float fast_sig(float x) {
    return fmaf(0.5f, fast_tanh(0.5f * x), 0.5f);
}

// Bank-swizzled smem row offset (floats). Properties:
//  - 16B aligned (all terms divisible by 4)
//  - in-warp group pair (veh, veh+8): delta = 200 floats -> bank shift 8 (disjoint chunks)
//  - driver phase: chunk start positions evenly distributed -> min phases
__device__ __forceinline__ int rowoff(int v) {
    return v * 24 + ((v >> 2) & 1) * 4 + (v >> 3) * 8;
}

// ---------- repack kernel ----------
__global__ void repack_kernel(const float* __restrict__ W,
                              const float* __restrict__ U,
                              const float* __restrict__ b,
                              const float* __restrict__ Wd,
                              const float* __restrict__ bd)
{
    int i = blockIdx.x * blockDim.x + threadIdx.x;
    if (i < 20 * 50) {
        int u = i / 50, s = i % 50;
        float a0 = 0.f, a1 = 0.f;
        if (s < 24) {                       // IF pair, slot s
            if (s < 3)       { a0 = W[s * 80 + u];        a1 = W[s * 80 + 20 + u]; }
            else if (s >= 4) { a0 = U[(s - 4) * 80 + u];  a1 = U[(s - 4) * 80 + 20 + u]; }
        } else if (s < 48) {                // GO pair, slot s-24
            int k = s - 24;
            if (k < 3)       { a0 = W[k * 80 + 40 + u];       a1 = W[k * 80 + 60 + u]; }
            else if (k >= 4) { a0 = U[(k - 4) * 80 + 40 + u]; a1 = U[(k - 4) * 80 + 60 + u]; }
        } else if (s == 48)  { a0 = b[u];      a1 = b[20 + u]; }
        else                 { a0 = b[40 + u]; a1 = b[60 + u]; }
        gWt[i] = make_float2(a0, a1);
    }
    if (i < 20)  gWd[i]  = Wd[i];
    if (i == 20) gWd[20] = bd[0];
}

__global__ __launch_bounds__(TPC, 2)
void rnncf_kernel(const float* __restrict__ lead_inputs,  // (NVEH, NT, 2)
                  const float* __restrict__ init_state,   // (NVEH, 2)
                  const float* __restrict__ h0,           // (NVEH, H)
                  const float* __restrict__ c0,           // (NVEH, H)
                  float* __restrict__ out,
                  int out_size)
{
    // Double-buffered activation rows: slots 0..2 = x, 3 = 0-pad, 4+j = h[j]
    __shared__ float xh[2][1600];

    const int tid = threadIdx.x;
    const int u   = tid % 20;          // unit owned by this thread
    const int grp = tid / 20;          // vehicle group (0..7)
    const int vb  = grp * VPT;         // local vehicle base

    // ---- load this unit's weights into registers (held for whole sim) ----
    ull wIF[24], wGO[24], bIF, bGO;
    {
        const ull* tb = reinterpret_cast<const ull*>(gWt) + u * 50;
#pragma unroll
        for (int k = 0; k < 24; ++k) { wIF[k] = tb[k]; wGO[k] = tb[24 + k]; }
        bIF = tb[48]; bGO = tb[49];
    }

    // ---- init state ----
    float cc[VPT];
#pragma unroll
    for (int v = 0; v < VPT; ++v) {
        int gveh = blockIdx.x * VPC + vb + v;
        cc[v] = c0[gveh * H + u];
        xh[0][rowoff(vb + v) + 4 + u] = h0[gveh * H + u];
    }

    // driver-only state (threads 0..63; warps 0,1)
    float pos = 0.f, spd = 0.f, bdv = 0.f;
    float wdr[20];
    const float2* mylead = nullptr;
    if (tid < VPC) {
        int gveh = blockIdx.x * VPC + tid;
        pos = init_state[2 * gveh];
        spd = init_state[2 * gveh + 1];
        mylead = reinterpret_cast<const float2*>(lead_inputs) + (size_t)gveh * NT;
        float2 l0 = mylead[0];
        int ro = rowoff(tid);
        xh[0][ro + 0] = (l0.x - pos) * (1.0f / 100.0f);
        xh[0][ro + 1] = spd * (1.0f / 40.0f);
        xh[0][ro + 2] = l0.y * (1.0f / 40.0f);
        xh[0][ro + 3] = 0.f;
        xh[1][ro + 3] = 0.f;
#pragma unroll
        for (int j = 0; j < 20; ++j) wdr[j] = gWd[j];
        bdv = gWd[20];
    }
    __syncthreads();

    const bool write_extras = (out_size >= NT * NVEH + NVEH + 2 * NVEH * H);
    float* outbase = out + blockIdx.x * VPC + tid;   // driver's output column

    int cb = 0;
#pragma unroll 1
    for (int t = 0; t < NT; ++t) {
        // driver prefetch of lead[t+1] (consumed in phase B, hidden under GEMM)
        float2 nl = make_float2(0.f, 0.f);
        if (tid < VPC) {
            int tn = (t + 1 < NT) ? (t + 1) : (NT - 1);
            nl = mylead[tn];
        }

        const float* rb = xh[cb];
        float*       wb = xh[cb ^ 1];

        // ---- Phase A: all threads, per-unit GEMM for 8 vehicles ----
#pragma unroll 2
        for (int v = 0; v < VPT; ++v) {
            const int ro = rowoff(vb + v);
            float4 r0 = *reinterpret_cast<const float4*>(rb + ro);
            float4 r1 = *reinterpret_cast<const float4*>(rb + ro + 4);
            float4 r2 = *reinterpret_cast<const float4*>(rb + ro + 8);
            float4 r3 = *reinterpret_cast<const float4*>(rb + ro + 12);
            float4 r4 = *reinterpret_cast<const float4*>(rb + ro + 16);
            float4 r5 = *reinterpret_cast<const float4*>(rb + ro + 20);

            ull ai = bIF, ag = bGO;
#define KK(kk, val) { ull md = dup2(val); ffma2(ai, wIF[kk], md); ffma2(ag, wGO[kk], md); }
            KK(0,  r0.x) KK(1,  r0.y) KK(2,  r0.z) KK(3,  r0.w)
            KK(4,  r1.x) KK(5,  r1.y) KK(6,  r1.z) KK(7,  r1.w)
            KK(8,  r2.x) KK(9,  r2.y) KK(10, r2.z) KK(11, r2.w)
            KK(12, r3.x) KK(13, r3.y) KK(14, r3.z) KK(15, r3.w)
            KK(16, r4.x) KK(17, r4.y) KK(18, r4.z) KK(19, r4.w)
            KK(20, r5.x) KK(21, r5.y) KK(22, r5.z) KK(23, r5.w)
#undef KK

            float si = fast_sig(lo32(ai));      // sig(i)
            float sf = fast_sig(hi32(ai));      // sig(f)
            float tg = fast_tanh(lo32(ag));     // tanh(g)
            float so = fast_sig(hi32(ag));      // sig(o)
            float cn = fmaf(sf, cc[v], si * tg);
            cc[v] = cn;
            wb[ro + 4 + u] = so * fast_tanh(cn);   // h_new
        }
        __syncthreads();

        // ---- Phase B: drivers (threads 0..63) scalar chain ----
        if (tid < VPC) {
            const int ro = rowoff(tid);
            float p = bdv;
#pragma unroll
            for (int j = 0; j < 20; ++j)
                p = fmaf(wb[ro + 4 + j], wdr[j], p);
            float a = fmaf(7.0f, p, -4.0f);          // (MAXA-MINA)*out + MINA
            spd = fmaf(0.1f, a, spd);
            pos = fmaf(0.1f, a, pos);
            outbase[(size_t)t * NVEH] = pos;          // coalesced per warp
            wb[ro + 0] = (nl.x - pos) * (1.0f / 100.0f);
            wb[ro + 1] = spd * (1.0f / 40.0f);
            wb[ro + 2] = nl.y * (1.0f / 40.0f);
        }
        __syncthreads();
        cb ^= 1;
    }

    if (write_extras) {
        if (tid < VPC)
            out[(size_t)NT * NVEH + blockIdx.x * VPC + tid] = spd;
        float* hout = out + (size_t)NT * NVEH + NVEH;
        float* cout = hout + (size_t)NVEH * H;
        const float* fb = xh[cb];
#pragma unroll
        for (int v = 0; v < VPT; ++v) {
            int gveh = blockIdx.x * VPC + vb + v;
            hout[gveh * H + u] = fb[rowoff(vb + v) + 4 + u];
            cout[gveh * H + u] = cc[v];
        }
    }
}

extern "C" void kernel_launch(void* const* d_in, const int* in_sizes, int n_in,
                              void* d_out, int out_size) {
    const float* lead_inputs = (const float*)d_in[0];
    const float* init_state  = (const float*)d_in[1];
    const float* h0          = (const float*)d_in[2];
    const float* c0          = (const float*)d_in[3];
    const float* W           = (const float*)d_in[4];
    const float* U           = (const float*)d_in[5];
    const float* b           = (const float*)d_in[6];
    const float* Wd          = (const float*)d_in[7];
    const float* bd          = (const float*)d_in[8];

    repack_kernel<<<1, 1024>>>(W, U, b, Wd, bd);
    rnncf_kernel<<<NCTA, TPC>>>(lead_inputs, init_state, h0, c0,
                                (float*)d_out, out_size);
}